// round 5
// baseline (speedup 1.0000x reference)
#include <cuda_runtime.h>
#include <cuda_bf16.h>

// DeepFilter: 5-tap complex FIR over first 256 freq bins + passthrough of the rest.
// spec:  [B=8][2][T=4096][F=481]  fp32
// coefs: [B=8][10][T=4096][256]   fp32   (10 = {real taps 0..4, imag taps 0..4})
// out:   [B=8][2][T=4096][F=481]  fp32
//
// DRAM-bound (~590 MB compulsory). Mapping: thread = freq bin (perfect lane
// coalescing), block = 2 consecutive time steps sharing a 6-row spec window.
// All 32 loads (12 spec + 20 coef) are front-batched into registers before any
// FMA to maximize per-thread MLP (R4 showed a 32-reg budget serializes them).

#define NUM_FREQS 256
#define FRAME_SIZE 5
#define B_DIM 8
#define T_DIM 4096
#define F_TOTAL 481
#define F_TAIL (F_TOTAL - NUM_FREQS)   // 225

__global__ __launch_bounds__(256, 2) void deepfilter_kernel(
    const float* __restrict__ spec,
    const float* __restrict__ coefs,
    float* __restrict__ out)
{
    const int blk = blockIdx.x;              // 0 .. 16383
    const int b   = blk >> 11;               // 2048 blocks per batch (T/2)
    const int t0  = (blk & 2047) << 1;       // 2 time steps per block
    const int f   = threadIdx.x;             // 0 .. 255

    const int spec_b0 = (b * 2) * T_DIM * F_TOTAL;     // real channel base
    const int spec_b1 = spec_b0 + T_DIM * F_TOTAL;     // imag channel base

    const int c_row  = ((b * 10) * T_DIM + t0) * NUM_FREQS + f;
    const int c_kstr = T_DIM * NUM_FREQS;    // per-tap stride

    // ---- Front-batched loads: issue everything before consuming anything ----

    // Spec window: ts = t0-4 .. t0+1 (6 rows, shared by both outputs)
    float pr[6], pi[6];
#pragma unroll
    for (int k = 0; k < 6; ++k) {
        const int ts = t0 - 4 + k;
        if (ts >= 0) {
            const int so = ts * F_TOTAL + f;
            pr[k] = spec[spec_b0 + so];
            pi[k] = spec[spec_b1 + so];
        } else {
            pr[k] = 0.0f;
            pi[k] = 0.0f;
        }
    }

    // Coefs: 2 time steps x (5 real + 5 imag) = 20 loads, streaming (read-once)
    float cr[2][FRAME_SIZE], ci[2][FRAME_SIZE];
#pragma unroll
    for (int tt = 0; tt < 2; ++tt) {
#pragma unroll
        for (int k = 0; k < FRAME_SIZE; ++k) {
            cr[tt][k] = __ldcs(&coefs[c_row + tt * NUM_FREQS + k * c_kstr]);
            ci[tt][k] = __ldcs(&coefs[c_row + tt * NUM_FREQS + (k + FRAME_SIZE) * c_kstr]);
        }
    }

    // ---- Compute ----
    float re0 = 0.f, im0 = 0.f, re1 = 0.f, im1 = 0.f;
#pragma unroll
    for (int k = 0; k < FRAME_SIZE; ++k) {
        re0 = fmaf(pr[k],      cr[0][k], re0);
        re0 = fmaf(-pi[k],     ci[0][k], re0);
        im0 = fmaf(pi[k],      cr[0][k], im0);
        im0 = fmaf(pr[k],      ci[0][k], im0);

        re1 = fmaf(pr[k + 1],  cr[1][k], re1);
        re1 = fmaf(-pi[k + 1], ci[1][k], re1);
        im1 = fmaf(pi[k + 1],  cr[1][k], im1);
        im1 = fmaf(pr[k + 1],  ci[1][k], im1);
    }

    const int orow = t0 * F_TOTAL + f;
    out[spec_b0 + orow]           = re0;
    out[spec_b1 + orow]           = im0;
    out[spec_b0 + orow + F_TOTAL] = re1;
    out[spec_b1 + orow + F_TOTAL] = im1;

    // Passthrough bins f = 256..480 for both channels and both rows:
    // 2 rows * 2 ch * 225 = 900 elems over 256 threads (divide-free).
#pragma unroll
    for (int u = 0; u < 4; ++u) {
        const int idx = threadIdx.x + u * 256;
        if (idx < 2 * 2 * F_TAIL) {
            const int r   = (idx >= 2 * F_TAIL) ? 1 : 0;
            const int rem = idx - r * (2 * F_TAIL);
            const int ch  = (rem >= F_TAIL) ? 1 : 0;
            const int j   = rem - ch * F_TAIL;
            const int o   = (b * 2 + ch) * T_DIM * F_TOTAL
                          + (t0 + r) * F_TOTAL + NUM_FREQS + j;
            out[o] = __ldcs(&spec[o]);
        }
    }
}

extern "C" void kernel_launch(void* const* d_in, const int* in_sizes, int n_in,
                              void* d_out, int out_size)
{
    const float* spec  = (const float*)d_in[0];
    const float* coefs = (const float*)d_in[1];
    float* out = (float*)d_out;

    dim3 grid(B_DIM * T_DIM / 2);
    dim3 block(256);
    deepfilter_kernel<<<grid, block>>>(spec, coefs, out);
}